// round 2
// baseline (speedup 1.0000x reference)
#include <cuda_runtime.h>

#define LQ 512
#define LLQ (512*512)

// channel-major scratch: [c][row] with row = flattened (i*L+m) / (m*L+j) / (i*L+j)
__device__ float g_a[(size_t)128 * LLQ];
__device__ float g_b[(size_t)128 * LLQ];
__device__ float g_k[(size_t)128 * LLQ];

__device__ __forceinline__ float sigmoidf_(float x) {
    return 1.0f / (1.0f + __expf(-x));
}

// ---------------------------------------------------------------------------
// Kernel 1: LN(z) + 4 gated projections -> a,b in channel-major layout
// block = 128 rows of the flattened [L*L, 128] input, 256 threads
// ---------------------------------------------------------------------------
__global__ void __launch_bounds__(256) k_ln_proj_ab(
    const float* __restrict__ z,
    const float* __restrict__ lnw, const float* __restrict__ lnb,
    const float* __restrict__ Wga, const float* __restrict__ bga,
    const float* __restrict__ Wla, const float* __restrict__ bla,
    const float* __restrict__ Wgb, const float* __restrict__ bgb,
    const float* __restrict__ Wlb, const float* __restrict__ blb)
{
    extern __shared__ float sm[];
    float* zn = sm;                  // [128][129]
    float* Ws = sm + 128 * 129;      // [128][128]
    float* sc = Ws + 128 * 128;      // [128][129]

    const int tid  = threadIdx.x;
    const int r0   = blockIdx.x * 128;
    const int lane = tid & 31, warp = tid >> 5;

    // ---- layernorm: one warp per row, 16 rows per warp ----
    const float w0 = lnw[lane], w1 = lnw[lane + 32], w2 = lnw[lane + 64], w3 = lnw[lane + 96];
    const float c0 = lnb[lane], c1 = lnb[lane + 32], c2 = lnb[lane + 64], c3 = lnb[lane + 96];
    for (int it = 0; it < 16; ++it) {
        int row = warp * 16 + it;
        const float* zr = z + (size_t)(r0 + row) * 128;
        float x0 = zr[lane], x1 = zr[lane + 32], x2 = zr[lane + 64], x3 = zr[lane + 96];
        float s = x0 + x1 + x2 + x3;
        float q = x0 * x0 + x1 * x1 + x2 * x2 + x3 * x3;
        #pragma unroll
        for (int o = 16; o > 0; o >>= 1) {
            s += __shfl_xor_sync(0xffffffffu, s, o);
            q += __shfl_xor_sync(0xffffffffu, q, o);
        }
        float mu  = s * (1.0f / 128.0f);
        float var = q * (1.0f / 128.0f) - mu * mu;
        float rs  = rsqrtf(var + 1e-5f);
        float* zo = zn + row * 129;
        zo[lane]      = (x0 - mu) * rs * w0 + c0;
        zo[lane + 32] = (x1 - mu) * rs * w1 + c1;
        zo[lane + 64] = (x2 - mu) * rs * w2 + c2;
        zo[lane + 96] = (x3 - mu) * rs * w3 + c3;
    }
    __syncthreads();

    const int tx = tid & 15, ty = tid >> 4;
    const int mb = ty * 8, cb = tx * 8;
    const float* znr = zn + mb * 129;

    #pragma unroll 1
    for (int p = 0; p < 2; ++p) {
        const float* Wg = p ? Wgb : Wga;
        const float* bg = p ? bgb : bga;
        const float* Wl = p ? Wlb : Wla;
        const float* bl = p ? blb : bla;
        float* dst = p ? g_b : g_a;

        // load gate weight
        for (int it = 0; it < 64; ++it) { int idx = it * 256 + tid; Ws[idx] = Wg[idx]; }
        __syncthreads();

        float acc[8][8];
        #pragma unroll
        for (int e = 0; e < 8; ++e)
            #pragma unroll
            for (int f = 0; f < 8; ++f) acc[e][f] = 0.0f;

        #pragma unroll 4
        for (int k = 0; k < 128; ++k) {
            float av[8];
            #pragma unroll
            for (int e = 0; e < 8; ++e) av[e] = znr[e * 129 + k];
            float4 q0 = *(const float4*)(Ws + k * 128 + cb);
            float4 q1 = *(const float4*)(Ws + k * 128 + cb + 4);
            float bv[8] = {q0.x, q0.y, q0.z, q0.w, q1.x, q1.y, q1.z, q1.w};
            #pragma unroll
            for (int e = 0; e < 8; ++e)
                #pragma unroll
                for (int f = 0; f < 8; ++f) acc[e][f] += av[e] * bv[f];
        }
        __syncthreads();   // Ws reads done everywhere

        {
            float bgv[8];
            #pragma unroll
            for (int f = 0; f < 8; ++f) bgv[f] = bg[cb + f];
            #pragma unroll
            for (int e = 0; e < 8; ++e)
                #pragma unroll
                for (int f = 0; f < 8; ++f)
                    sc[(mb + e) * 129 + cb + f] = sigmoidf_(acc[e][f] + bgv[f]);
        }
        // reload linear weight
        for (int it = 0; it < 64; ++it) { int idx = it * 256 + tid; Ws[idx] = Wl[idx]; }
        __syncthreads();

        #pragma unroll
        for (int e = 0; e < 8; ++e)
            #pragma unroll
            for (int f = 0; f < 8; ++f) acc[e][f] = 0.0f;

        #pragma unroll 4
        for (int k = 0; k < 128; ++k) {
            float av[8];
            #pragma unroll
            for (int e = 0; e < 8; ++e) av[e] = znr[e * 129 + k];
            float4 q0 = *(const float4*)(Ws + k * 128 + cb);
            float4 q1 = *(const float4*)(Ws + k * 128 + cb + 4);
            float bv[8] = {q0.x, q0.y, q0.z, q0.w, q1.x, q1.y, q1.z, q1.w};
            #pragma unroll
            for (int e = 0; e < 8; ++e)
                #pragma unroll
                for (int f = 0; f < 8; ++f) acc[e][f] += av[e] * bv[f];
        }

        {
            float blv[8];
            #pragma unroll
            for (int f = 0; f < 8; ++f) blv[f] = bl[cb + f];
            #pragma unroll
            for (int e = 0; e < 8; ++e)
                #pragma unroll
                for (int f = 0; f < 8; ++f) {
                    int s_idx = (mb + e) * 129 + cb + f;
                    sc[s_idx] = sc[s_idx] * (acc[e][f] + blv[f]);   // own slot, no race
                }
        }
        __syncthreads();

        // transposed, coalesced store: dst[c*LL + r0 + m]
        for (int it = 0; it < 64; ++it) {
            int idx = it * 256 + tid;
            int m = idx & 127;
            int c = idx >> 7;
            dst[(size_t)c * LLQ + r0 + m] = sc[m * 129 + c];
        }
        __syncthreads();
    }
}

// ---------------------------------------------------------------------------
// Kernel 2: per-channel 512x512x512 GEMM  K_c = A_c @ B_c (row-major, contiguous)
// BM=BN=128, BK=16, 256 threads, 8x8 per thread
// ---------------------------------------------------------------------------
__global__ void __launch_bounds__(256) k_einsum()
{
    __shared__ float As[128 * 17];
    __shared__ float Bs[16 * 128];

    const int c  = blockIdx.z;
    const int i0 = blockIdx.y * 128;
    const int j0 = blockIdx.x * 128;
    const float* A = g_a + (size_t)c * LLQ;
    const float* B = g_b + (size_t)c * LLQ;
    float*       K = g_k + (size_t)c * LLQ;

    const int tid = threadIdx.x;
    const int tx = tid & 15, ty = tid >> 4;

    const int arow = tid >> 1,  acol = (tid & 1) * 8;
    const int brow = tid >> 4,  bcol = (tid & 15) * 8;

    float acc[8][8];
    #pragma unroll
    for (int e = 0; e < 8; ++e)
        #pragma unroll
        for (int f = 0; f < 8; ++f) acc[e][f] = 0.0f;

    for (int kt = 0; kt < 32; ++kt) {
        int k0 = kt * 16;
        float4 a0 = *(const float4*)(A + (size_t)(i0 + arow) * LQ + k0 + acol);
        float4 a1 = *(const float4*)(A + (size_t)(i0 + arow) * LQ + k0 + acol + 4);
        float* asr = As + arow * 17 + acol;
        asr[0] = a0.x; asr[1] = a0.y; asr[2] = a0.z; asr[3] = a0.w;
        asr[4] = a1.x; asr[5] = a1.y; asr[6] = a1.z; asr[7] = a1.w;

        float4 v0 = *(const float4*)(B + (size_t)(k0 + brow) * LQ + j0 + bcol);
        float4 v1 = *(const float4*)(B + (size_t)(k0 + brow) * LQ + j0 + bcol + 4);
        *(float4*)(Bs + brow * 128 + bcol)     = v0;
        *(float4*)(Bs + brow * 128 + bcol + 4) = v1;
        __syncthreads();

        const float* asb = As + ty * 8 * 17;
        #pragma unroll
        for (int k = 0; k < 16; ++k) {
            float av[8];
            #pragma unroll
            for (int e = 0; e < 8; ++e) av[e] = asb[e * 17 + k];
            float4 q0 = *(const float4*)(Bs + k * 128 + tx * 8);
            float4 q1 = *(const float4*)(Bs + k * 128 + tx * 8 + 4);
            float bv[8] = {q0.x, q0.y, q0.z, q0.w, q1.x, q1.y, q1.z, q1.w};
            #pragma unroll
            for (int e = 0; e < 8; ++e)
                #pragma unroll
                for (int f = 0; f < 8; ++f) acc[e][f] += av[e] * bv[f];
        }
        __syncthreads();
    }

    #pragma unroll
    for (int e = 0; e < 8; ++e) {
        float* kr = K + (size_t)(i0 + ty * 8 + e) * LQ + j0 + tx * 8;
        float4 o0 = make_float4(acc[e][0], acc[e][1], acc[e][2], acc[e][3]);
        float4 o1 = make_float4(acc[e][4], acc[e][5], acc[e][6], acc[e][7]);
        *(float4*)(kr)     = o0;
        *(float4*)(kr + 4) = o1;
    }
}

// ---------------------------------------------------------------------------
// Kernel 3: out = sigmoid(LN(z)@Wgo + bgo) * (LN(k)@Wlo + blo)
// ---------------------------------------------------------------------------
__global__ void __launch_bounds__(256) k_final(
    const float* __restrict__ z,
    const float* __restrict__ lnw, const float* __restrict__ lnb,
    const float* __restrict__ lnow, const float* __restrict__ lnob,
    const float* __restrict__ Wgo, const float* __restrict__ bgo,
    const float* __restrict__ Wlo, const float* __restrict__ blo,
    float* __restrict__ out)
{
    extern __shared__ float sm[];
    float* zn = sm;                  // [128][129]  (later reused to hold the gate)
    float* kn = sm + 128 * 129;      // [128][129]
    float* Ws = kn + 128 * 129;      // [128][128]

    const int tid  = threadIdx.x;
    const int r0   = blockIdx.x * 128;
    const int i    = r0 >> 9;
    const int j0   = r0 & 511;
    const int lane = tid & 31, warp = tid >> 5;

    // LN(z)
    {
        const float w0 = lnw[lane], w1 = lnw[lane + 32], w2 = lnw[lane + 64], w3 = lnw[lane + 96];
        const float c0 = lnb[lane], c1 = lnb[lane + 32], c2 = lnb[lane + 64], c3 = lnb[lane + 96];
        for (int it = 0; it < 16; ++it) {
            int row = warp * 16 + it;
            const float* zr = z + (size_t)(r0 + row) * 128;
            float x0 = zr[lane], x1 = zr[lane + 32], x2 = zr[lane + 64], x3 = zr[lane + 96];
            float s = x0 + x1 + x2 + x3;
            float q = x0 * x0 + x1 * x1 + x2 * x2 + x3 * x3;
            #pragma unroll
            for (int o = 16; o > 0; o >>= 1) {
                s += __shfl_xor_sync(0xffffffffu, s, o);
                q += __shfl_xor_sync(0xffffffffu, q, o);
            }
            float mu  = s * (1.0f / 128.0f);
            float var = q * (1.0f / 128.0f) - mu * mu;
            float rs  = rsqrtf(var + 1e-5f);
            float* zo = zn + row * 129;
            zo[lane]      = (x0 - mu) * rs * w0 + c0;
            zo[lane + 32] = (x1 - mu) * rs * w1 + c1;
            zo[lane + 64] = (x2 - mu) * rs * w2 + c2;
            zo[lane + 96] = (x3 - mu) * rs * w3 + c3;
        }
    }

    // gather k tile from channel-major g_k -> kn[jl][c]
    for (int it = 0; it < 64; ++it) {
        int idx = it * 256 + tid;
        int jl = idx & 127;
        int c  = idx >> 7;
        kn[jl * 129 + c] = g_k[(size_t)c * LLQ + (size_t)i * LQ + j0 + jl];
    }
    __syncthreads();

    // LN(k) in place
    {
        const float w0 = lnow[lane], w1 = lnow[lane + 32], w2 = lnow[lane + 64], w3 = lnow[lane + 96];
        const float c0 = lnob[lane], c1 = lnob[lane + 32], c2 = lnob[lane + 64], c3 = lnob[lane + 96];
        for (int it = 0; it < 16; ++it) {
            int row = warp * 16 + it;
            float* kr = kn + row * 129;
            float x0 = kr[lane], x1 = kr[lane + 32], x2 = kr[lane + 64], x3 = kr[lane + 96];
            float s = x0 + x1 + x2 + x3;
            float q = x0 * x0 + x1 * x1 + x2 * x2 + x3 * x3;
            #pragma unroll
            for (int o = 16; o > 0; o >>= 1) {
                s += __shfl_xor_sync(0xffffffffu, s, o);
                q += __shfl_xor_sync(0xffffffffu, q, o);
            }
            float mu  = s * (1.0f / 128.0f);
            float var = q * (1.0f / 128.0f) - mu * mu;
            float rs  = rsqrtf(var + 1e-5f);
            kr[lane]      = (x0 - mu) * rs * w0 + c0;
            kr[lane + 32] = (x1 - mu) * rs * w1 + c1;
            kr[lane + 64] = (x2 - mu) * rs * w2 + c2;
            kr[lane + 96] = (x3 - mu) * rs * w3 + c3;
        }
    }

    const int tx = tid & 15, ty = tid >> 4;
    const int mb = ty * 8, cb = tx * 8;

    // gate GEMM: zn @ Wgo
    for (int it = 0; it < 64; ++it) { int idx = it * 256 + tid; Ws[idx] = Wgo[idx]; }
    __syncthreads();

    float acc[8][8];
    #pragma unroll
    for (int e = 0; e < 8; ++e)
        #pragma unroll
        for (int f = 0; f < 8; ++f) acc[e][f] = 0.0f;

    {
        const float* znr = zn + mb * 129;
        #pragma unroll 4
        for (int k = 0; k < 128; ++k) {
            float av[8];
            #pragma unroll
            for (int e = 0; e < 8; ++e) av[e] = znr[e * 129 + k];
            float4 q0 = *(const float4*)(Ws + k * 128 + cb);
            float4 q1 = *(const float4*)(Ws + k * 128 + cb + 4);
            float bv[8] = {q0.x, q0.y, q0.z, q0.w, q1.x, q1.y, q1.z, q1.w};
            #pragma unroll
            for (int e = 0; e < 8; ++e)
                #pragma unroll
                for (int f = 0; f < 8; ++f) acc[e][f] += av[e] * bv[f];
        }
    }
    __syncthreads();   // all zn reads + Ws reads done

    {
        float bgv[8];
        #pragma unroll
        for (int f = 0; f < 8; ++f) bgv[f] = bgo[cb + f];
        #pragma unroll
        for (int e = 0; e < 8; ++e)
            #pragma unroll
            for (int f = 0; f < 8; ++f)
                zn[(mb + e) * 129 + cb + f] = sigmoidf_(acc[e][f] + bgv[f]);  // zn now = gate
    }
    for (int it = 0; it < 64; ++it) { int idx = it * 256 + tid; Ws[idx] = Wlo[idx]; }
    __syncthreads();

    #pragma unroll
    for (int e = 0; e < 8; ++e)
        #pragma unroll
        for (int f = 0; f < 8; ++f) acc[e][f] = 0.0f;

    {
        const float* knr = kn + mb * 129;
        #pragma unroll 4
        for (int k = 0; k < 128; ++k) {
            float av[8];
            #pragma unroll
            for (int e = 0; e < 8; ++e) av[e] = knr[e * 129 + k];
            float4 q0 = *(const float4*)(Ws + k * 128 + cb);
            float4 q1 = *(const float4*)(Ws + k * 128 + cb + 4);
            float bv[8] = {q0.x, q0.y, q0.z, q0.w, q1.x, q1.y, q1.z, q1.w};
            #pragma unroll
            for (int e = 0; e < 8; ++e)
                #pragma unroll
                for (int f = 0; f < 8; ++f) acc[e][f] += av[e] * bv[f];
        }
    }

    {
        float blv[8];
        #pragma unroll
        for (int f = 0; f < 8; ++f) blv[f] = blo[cb + f];
        #pragma unroll
        for (int e = 0; e < 8; ++e) {
            float v[8];
            #pragma unroll
            for (int f = 0; f < 8; ++f)
                v[f] = zn[(mb + e) * 129 + cb + f] * (acc[e][f] + blv[f]);
            float* orow = out + (size_t)(r0 + mb + e) * 128 + cb;
            *(float4*)(orow)     = make_float4(v[0], v[1], v[2], v[3]);
            *(float4*)(orow + 4) = make_float4(v[4], v[5], v[6], v[7]);
        }
    }
}

// ---------------------------------------------------------------------------
extern "C" void kernel_launch(void* const* d_in, const int* in_sizes, int n_in,
                              void* d_out, int out_size)
{
    const float* z    = (const float*)d_in[0];
    const float* lnw  = (const float*)d_in[1];
    const float* lnb  = (const float*)d_in[2];
    const float* Wga  = (const float*)d_in[3];
    const float* bga  = (const float*)d_in[4];
    const float* Wla  = (const float*)d_in[5];
    const float* bla  = (const float*)d_in[6];
    const float* Wgb  = (const float*)d_in[7];
    const float* bgb  = (const float*)d_in[8];
    const float* Wlb  = (const float*)d_in[9];
    const float* blb  = (const float*)d_in[10];
    const float* lnow = (const float*)d_in[11];
    const float* lnob = (const float*)d_in[12];
    const float* Wgo  = (const float*)d_in[13];
    const float* bgo  = (const float*)d_in[14];
    const float* Wlo  = (const float*)d_in[15];
    const float* blo  = (const float*)d_in[16];
    float* out = (float*)d_out;

    const size_t smemA = (size_t)(128 * 129 + 128 * 128 + 128 * 129) * sizeof(float);
    cudaFuncSetAttribute(k_ln_proj_ab, cudaFuncAttributeMaxDynamicSharedMemorySize, (int)smemA);
    cudaFuncSetAttribute(k_final,      cudaFuncAttributeMaxDynamicSharedMemorySize, (int)smemA);

    k_ln_proj_ab<<<2048, 256, smemA>>>(z, lnw, lnb, Wga, bga, Wla, bla, Wgb, bgb, Wlb, blb);
    k_einsum<<<dim3(4, 4, 128), 256>>>();
    k_final<<<2048, 256, smemA>>>(z, lnw, lnb, lnow, lnob, Wgo, bgo, Wlo, blo, out);
}

// round 4
// speedup vs baseline: 1.2704x; 1.2704x over previous
#include <cuda_runtime.h>
#include <cstdint>

#define LQ 512
#define LLQ (512*512)

// channel-major scratch
__device__ float g_a [(size_t)128 * LLQ];   // a [c][i][m]   (tf32-rounded)
__device__ float g_b [(size_t)128 * LLQ];   // b [c][m][j]   (fp32)
__device__ float g_bt[(size_t)128 * LLQ];   // b^T [c][j][m] (tf32-rounded)
__device__ float g_k [(size_t)128 * LLQ];   // k [c][i][j]   (fp32)

__device__ __forceinline__ float sigmoidf_(float x) {
    return 1.0f / (1.0f + __expf(-x));
}

__device__ __forceinline__ float to_tf32(float x) {
    uint32_t u;
    asm("cvt.rna.tf32.f32 %0, %1;" : "=r"(u) : "f"(x));
    return __uint_as_float(u);
}

// warp-level tf32 MMA: D(16x8) += A(16x8) * B(8x8), row.col
__device__ __forceinline__ void mma_tf32(float* d, uint32_t a0, uint32_t a1, uint32_t a2, uint32_t a3,
                                         uint32_t b0, uint32_t b1) {
    asm volatile(
        "mma.sync.aligned.m16n8k8.row.col.f32.tf32.tf32.f32 "
        "{%0,%1,%2,%3}, {%4,%5,%6,%7}, {%8,%9}, {%0,%1,%2,%3};"
        : "+f"(d[0]), "+f"(d[1]), "+f"(d[2]), "+f"(d[3])
        : "r"(a0), "r"(a1), "r"(a2), "r"(a3), "r"(b0), "r"(b1));
}

// ---------------------------------------------------------------------------
// Kernel 1: LN(z) + 4 gated projections -> a,b channel-major (a tf32-rounded)
// ---------------------------------------------------------------------------
__global__ void __launch_bounds__(256) k_ln_proj_ab(
    const float* __restrict__ z,
    const float* __restrict__ lnw, const float* __restrict__ lnb,
    const float* __restrict__ Wga, const float* __restrict__ bga,
    const float* __restrict__ Wla, const float* __restrict__ bla,
    const float* __restrict__ Wgb, const float* __restrict__ bgb,
    const float* __restrict__ Wlb, const float* __restrict__ blb)
{
    extern __shared__ float sm[];
    float* zn = sm;                  // [128][129]
    float* Ws = sm + 128 * 129;      // [128][128]
    float* sc = Ws + 128 * 128;      // [128][129]

    const int tid  = threadIdx.x;
    const int r0   = blockIdx.x * 128;
    const int lane = tid & 31, warp = tid >> 5;

    const float w0 = lnw[lane], w1 = lnw[lane + 32], w2 = lnw[lane + 64], w3 = lnw[lane + 96];
    const float c0 = lnb[lane], c1 = lnb[lane + 32], c2 = lnb[lane + 64], c3 = lnb[lane + 96];
    for (int it = 0; it < 16; ++it) {
        int row = warp * 16 + it;
        const float* zr = z + (size_t)(r0 + row) * 128;
        float x0 = zr[lane], x1 = zr[lane + 32], x2 = zr[lane + 64], x3 = zr[lane + 96];
        float s = x0 + x1 + x2 + x3;
        float q = x0 * x0 + x1 * x1 + x2 * x2 + x3 * x3;
        #pragma unroll
        for (int o = 16; o > 0; o >>= 1) {
            s += __shfl_xor_sync(0xffffffffu, s, o);
            q += __shfl_xor_sync(0xffffffffu, q, o);
        }
        float mu  = s * (1.0f / 128.0f);
        float var = q * (1.0f / 128.0f) - mu * mu;
        float rs  = rsqrtf(var + 1e-5f);
        float* zo = zn + row * 129;
        zo[lane]      = (x0 - mu) * rs * w0 + c0;
        zo[lane + 32] = (x1 - mu) * rs * w1 + c1;
        zo[lane + 64] = (x2 - mu) * rs * w2 + c2;
        zo[lane + 96] = (x3 - mu) * rs * w3 + c3;
    }
    __syncthreads();

    const int tx = tid & 15, ty = tid >> 4;
    const int mb = ty * 8, cb = tx * 8;
    const float* znr = zn + mb * 129;

    #pragma unroll 1
    for (int p = 0; p < 2; ++p) {
        const float* Wg = p ? Wgb : Wga;
        const float* bg = p ? bgb : bga;
        const float* Wl = p ? Wlb : Wla;
        const float* bl = p ? blb : bla;
        float* dst = p ? g_b : g_a;

        for (int it = 0; it < 64; ++it) { int idx = it * 256 + tid; Ws[idx] = Wg[idx]; }
        __syncthreads();

        float acc[8][8];
        #pragma unroll
        for (int e = 0; e < 8; ++e)
            #pragma unroll
            for (int f = 0; f < 8; ++f) acc[e][f] = 0.0f;

        #pragma unroll 4
        for (int k = 0; k < 128; ++k) {
            float av[8];
            #pragma unroll
            for (int e = 0; e < 8; ++e) av[e] = znr[e * 129 + k];
            float4 q0 = *(const float4*)(Ws + k * 128 + cb);
            float4 q1 = *(const float4*)(Ws + k * 128 + cb + 4);
            float bv[8] = {q0.x, q0.y, q0.z, q0.w, q1.x, q1.y, q1.z, q1.w};
            #pragma unroll
            for (int e = 0; e < 8; ++e)
                #pragma unroll
                for (int f = 0; f < 8; ++f) acc[e][f] += av[e] * bv[f];
        }
        __syncthreads();

        {
            float bgv[8];
            #pragma unroll
            for (int f = 0; f < 8; ++f) bgv[f] = bg[cb + f];
            #pragma unroll
            for (int e = 0; e < 8; ++e)
                #pragma unroll
                for (int f = 0; f < 8; ++f)
                    sc[(mb + e) * 129 + cb + f] = sigmoidf_(acc[e][f] + bgv[f]);
        }
        for (int it = 0; it < 64; ++it) { int idx = it * 256 + tid; Ws[idx] = Wl[idx]; }
        __syncthreads();

        #pragma unroll
        for (int e = 0; e < 8; ++e)
            #pragma unroll
            for (int f = 0; f < 8; ++f) acc[e][f] = 0.0f;

        #pragma unroll 4
        for (int k = 0; k < 128; ++k) {
            float av[8];
            #pragma unroll
            for (int e = 0; e < 8; ++e) av[e] = znr[e * 129 + k];
            float4 q0 = *(const float4*)(Ws + k * 128 + cb);
            float4 q1 = *(const float4*)(Ws + k * 128 + cb + 4);
            float bv[8] = {q0.x, q0.y, q0.z, q0.w, q1.x, q1.y, q1.z, q1.w};
            #pragma unroll
            for (int e = 0; e < 8; ++e)
                #pragma unroll
                for (int f = 0; f < 8; ++f) acc[e][f] += av[e] * bv[f];
        }

        {
            float blv[8];
            #pragma unroll
            for (int f = 0; f < 8; ++f) blv[f] = bl[cb + f];
            #pragma unroll
            for (int e = 0; e < 8; ++e)
                #pragma unroll
                for (int f = 0; f < 8; ++f) {
                    int s_idx = (mb + e) * 129 + cb + f;
                    sc[s_idx] = sc[s_idx] * (acc[e][f] + blv[f]);
                }
        }
        __syncthreads();

        if (p == 0) {
            for (int it = 0; it < 64; ++it) {
                int idx = it * 256 + tid;
                int m = idx & 127, c = idx >> 7;
                dst[(size_t)c * LLQ + r0 + m] = to_tf32(sc[m * 129 + c]);
            }
        } else {
            for (int it = 0; it < 64; ++it) {
                int idx = it * 256 + tid;
                int m = idx & 127, c = idx >> 7;
                dst[(size_t)c * LLQ + r0 + m] = sc[m * 129 + c];
            }
        }
        __syncthreads();
    }
}

// ---------------------------------------------------------------------------
// Transpose: g_b [c][m][j] -> g_bt [c][j][m], tf32-rounded
// ---------------------------------------------------------------------------
__global__ void __launch_bounds__(256) k_transpose_b()
{
    __shared__ float t[32][33];
    const int c  = blockIdx.z;
    const int m0 = blockIdx.y * 32;
    const int j0 = blockIdx.x * 32;
    const int tx = threadIdx.x & 31, ty = threadIdx.x >> 5;  // ty in [0,8)

    const float* src = g_b + (size_t)c * LLQ;
    float*       dst = g_bt + (size_t)c * LLQ;

    #pragma unroll
    for (int r = 0; r < 4; ++r) {
        int m = ty * 4 + r;
        t[m][tx] = src[(size_t)(m0 + m) * LQ + j0 + tx];
    }
    __syncthreads();
    #pragma unroll
    for (int r = 0; r < 4; ++r) {
        int j = ty * 4 + r;
        dst[(size_t)(j0 + j) * LQ + m0 + tx] = to_tf32(t[tx][j]);
    }
}

// ---------------------------------------------------------------------------
// Kernel 2: mma.sync TF32 einsum. Per CTA: 128x128 tile of K_c = A_c @ B_c^T
// A = g_a [c][i][m] (row-major K), B = g_bt [c][j][m] (col-major fragment src)
// 256 threads = 8 warps (4 m x 2 n), warp tile 32x64, BK=32, reg prefetch.
// ---------------------------------------------------------------------------
#define EPAD 36   // smem row stride in floats (36 % 32 == 4 -> conflict-free frags)

__global__ void __launch_bounds__(256, 2) k_einsum_mma()
{
    __shared__ float As[128 * EPAD];
    __shared__ float Bs[128 * EPAD];

    const int tid  = threadIdx.x;
    const int lane = tid & 31, warp = tid >> 5;
    const int wm = warp & 3;        // 4 m-tiles of 32
    const int wn = warp >> 2;       // 2 n-tiles of 64
    const int c  = blockIdx.z;
    const int i0 = blockIdx.y * 128;
    const int j0 = blockIdx.x * 128;

    const float* A  = g_a  + (size_t)c * LLQ;
    const float* Bt = g_bt + (size_t)c * LLQ;

    // load indexing: 1024 float4 per operand tile, 4 per thread
    const int lrow = tid >> 1;            // pairs: each thread covers rows tid/2 (x4)
    // simpler: idx = r*256 + tid ; row = idx>>3 ; q = idx&7
    float4 pa[4], pb[4];

    #pragma unroll
    for (int r = 0; r < 4; ++r) {
        int idx = r * 256 + tid;
        int row = idx >> 3, q = idx & 7;
        pa[r] = *(const float4*)(A  + (size_t)(i0 + row) * LQ + q * 4);
        pb[r] = *(const float4*)(Bt + (size_t)(j0 + row) * LQ + q * 4);
    }

    float acc[2][8][4];
    #pragma unroll
    for (int t = 0; t < 2; ++t)
        #pragma unroll
        for (int u = 0; u < 8; ++u)
            #pragma unroll
            for (int v = 0; v < 4; ++v) acc[t][u][v] = 0.0f;

    const int arow0 = wm * 32 + (lane >> 2);
    const int acol  = lane & 3;
    const int brow0 = wn * 64 + (lane >> 2);

    #pragma unroll 1
    for (int kt = 0; kt < 16; ++kt) {
        // stage current chunk
        #pragma unroll
        for (int r = 0; r < 4; ++r) {
            int idx = r * 256 + tid;
            int row = idx >> 3, q = idx & 7;
            *(float4*)(As + row * EPAD + q * 4) = pa[r];
            *(float4*)(Bs + row * EPAD + q * 4) = pb[r];
        }
        __syncthreads();

        // prefetch next chunk
        if (kt < 15) {
            int k0 = (kt + 1) * 32;
            #pragma unroll
            for (int r = 0; r < 4; ++r) {
                int idx = r * 256 + tid;
                int row = idx >> 3, q = idx & 7;
                pa[r] = *(const float4*)(A  + (size_t)(i0 + row) * LQ + k0 + q * 4);
                pb[r] = *(const float4*)(Bt + (size_t)(j0 + row) * LQ + k0 + q * 4);
            }
        }

        // compute: 4 k-steps of 8
        #pragma unroll
        for (int ks = 0; ks < 4; ++ks) {
            const int k = ks * 8;
            uint32_t af[2][4];
            #pragma unroll
            for (int t = 0; t < 2; ++t) {
                int ra = arow0 + t * 16;
                af[t][0] = __float_as_uint(As[ra * EPAD + k + acol]);
                af[t][1] = __float_as_uint(As[(ra + 8) * EPAD + k + acol]);
                af[t][2] = __float_as_uint(As[ra * EPAD + k + acol + 4]);
                af[t][3] = __float_as_uint(As[(ra + 8) * EPAD + k + acol + 4]);
            }
            #pragma unroll
            for (int u = 0; u < 8; ++u) {
                int rb = brow0 + u * 8;
                uint32_t b0 = __float_as_uint(Bs[rb * EPAD + k + acol]);
                uint32_t b1 = __float_as_uint(Bs[rb * EPAD + k + acol + 4]);
                mma_tf32(acc[0][u], af[0][0], af[0][1], af[0][2], af[0][3], b0, b1);
                mma_tf32(acc[1][u], af[1][0], af[1][1], af[1][2], af[1][3], b0, b1);
            }
        }
        __syncthreads();
    }

    // epilogue: c0 (row, col2), c1 (row, col2+1), c2/c3 (row+8)
    float* K = g_k + (size_t)c * LLQ;
    const int orow = i0 + wm * 32 + (lane >> 2);
    const int ocol = j0 + wn * 64 + (lane & 3) * 2;
    #pragma unroll
    for (int t = 0; t < 2; ++t) {
        #pragma unroll
        for (int u = 0; u < 8; ++u) {
            float* p0 = K + (size_t)(orow + t * 16)     * LQ + ocol + u * 8;
            float* p1 = K + (size_t)(orow + t * 16 + 8) * LQ + ocol + u * 8;
            *(float2*)p0 = make_float2(acc[t][u][0], acc[t][u][1]);
            *(float2*)p1 = make_float2(acc[t][u][2], acc[t][u][3]);
        }
    }
}

// ---------------------------------------------------------------------------
// Kernel 3: out = sigmoid(LN(z)@Wgo + bgo) * (LN(k)@Wlo + blo)
// ---------------------------------------------------------------------------
__global__ void __launch_bounds__(256) k_final(
    const float* __restrict__ z,
    const float* __restrict__ lnw, const float* __restrict__ lnb,
    const float* __restrict__ lnow, const float* __restrict__ lnob,
    const float* __restrict__ Wgo, const float* __restrict__ bgo,
    const float* __restrict__ Wlo, const float* __restrict__ blo,
    float* __restrict__ out)
{
    extern __shared__ float sm[];
    float* zn = sm;
    float* kn = sm + 128 * 129;
    float* Ws = kn + 128 * 129;

    const int tid  = threadIdx.x;
    const int r0   = blockIdx.x * 128;
    const int i    = r0 >> 9;
    const int j0   = r0 & 511;
    const int lane = tid & 31, warp = tid >> 5;

    {
        const float w0 = lnw[lane], w1 = lnw[lane + 32], w2 = lnw[lane + 64], w3 = lnw[lane + 96];
        const float c0 = lnb[lane], c1 = lnb[lane + 32], c2 = lnb[lane + 64], c3 = lnb[lane + 96];
        for (int it = 0; it < 16; ++it) {
            int row = warp * 16 + it;
            const float* zr = z + (size_t)(r0 + row) * 128;
            float x0 = zr[lane], x1 = zr[lane + 32], x2 = zr[lane + 64], x3 = zr[lane + 96];
            float s = x0 + x1 + x2 + x3;
            float q = x0 * x0 + x1 * x1 + x2 * x2 + x3 * x3;
            #pragma unroll
            for (int o = 16; o > 0; o >>= 1) {
                s += __shfl_xor_sync(0xffffffffu, s, o);
                q += __shfl_xor_sync(0xffffffffu, q, o);
            }
            float mu  = s * (1.0f / 128.0f);
            float var = q * (1.0f / 128.0f) - mu * mu;
            float rs  = rsqrtf(var + 1e-5f);
            float* zo = zn + row * 129;
            zo[lane]      = (x0 - mu) * rs * w0 + c0;
            zo[lane + 32] = (x1 - mu) * rs * w1 + c1;
            zo[lane + 64] = (x2 - mu) * rs * w2 + c2;
            zo[lane + 96] = (x3 - mu) * rs * w3 + c3;
        }
    }

    for (int it = 0; it < 64; ++it) {
        int idx = it * 256 + tid;
        int jl = idx & 127;
        int c  = idx >> 7;
        kn[jl * 129 + c] = g_k[(size_t)c * LLQ + (size_t)i * LQ + j0 + jl];
    }
    __syncthreads();

    {
        const float w0 = lnow[lane], w1 = lnow[lane + 32], w2 = lnow[lane + 64], w3 = lnow[lane + 96];
        const float c0 = lnob[lane], c1 = lnob[lane + 32], c2 = lnob[lane + 64], c3 = lnob[lane + 96];
        for (int it = 0; it < 16; ++it) {
            int row = warp * 16 + it;
            float* kr = kn + row * 129;
            float x0 = kr[lane], x1 = kr[lane + 32], x2 = kr[lane + 64], x3 = kr[lane + 96];
            float s = x0 + x1 + x2 + x3;
            float q = x0 * x0 + x1 * x1 + x2 * x2 + x3 * x3;
            #pragma unroll
            for (int o = 16; o > 0; o >>= 1) {
                s += __shfl_xor_sync(0xffffffffu, s, o);
                q += __shfl_xor_sync(0xffffffffu, q, o);
            }
            float mu  = s * (1.0f / 128.0f);
            float var = q * (1.0f / 128.0f) - mu * mu;
            float rs  = rsqrtf(var + 1e-5f);
            kr[lane]      = (x0 - mu) * rs * w0 + c0;
            kr[lane + 32] = (x1 - mu) * rs * w1 + c1;
            kr[lane + 64] = (x2 - mu) * rs * w2 + c2;
            kr[lane + 96] = (x3 - mu) * rs * w3 + c3;
        }
    }

    const int tx = tid & 15, ty = tid >> 4;
    const int mb = ty * 8, cb = tx * 8;

    for (int it = 0; it < 64; ++it) { int idx = it * 256 + tid; Ws[idx] = Wgo[idx]; }
    __syncthreads();

    float acc[8][8];
    #pragma unroll
    for (int e = 0; e < 8; ++e)
        #pragma unroll
        for (int f = 0; f < 8; ++f) acc[e][f] = 0.0f;

    {
        const float* znr = zn + mb * 129;
        #pragma unroll 4
        for (int k = 0; k < 128; ++k) {
            float av[8];
            #pragma unroll
            for (int e = 0; e < 8; ++e) av[e] = znr[e * 129 + k];
            float4 q0 = *(const float4*)(Ws + k * 128 + cb);
            float4 q1 = *(const float4*)(Ws + k * 128 + cb + 4);
            float bv[8] = {q0.x, q0.y, q0.z, q0.w, q1.x, q1.y, q1.z, q1.w};
            #pragma unroll
            for (int e = 0; e < 8; ++e)
                #pragma unroll
                for (int f = 0; f < 8; ++f) acc[e][f] += av[e] * bv[f];
        }
    }
    __syncthreads();

    {
        float bgv[8];
        #pragma unroll
        for (int f = 0; f < 8; ++f) bgv[f] = bgo[cb + f];
        #pragma unroll
        for (int e = 0; e < 8; ++e)
            #pragma unroll
            for (int f = 0; f < 8; ++f)
                zn[(mb + e) * 129 + cb + f] = sigmoidf_(acc[e][f] + bgv[f]);
    }
    for (int it = 0; it < 64; ++it) { int idx = it * 256 + tid; Ws[idx] = Wlo[idx]; }
    __syncthreads();

    #pragma unroll
    for (int e = 0; e < 8; ++e)
        #pragma unroll
        for (int f = 0; f < 8; ++f) acc[e][f] = 0.0f;

    {
        const float* knr = kn + mb * 129;
        #pragma unroll 4
        for (int k = 0; k < 128; ++k) {
            float av[8];
            #pragma unroll
            for (int e = 0; e < 8; ++e) av[e] = knr[e * 129 + k];
            float4 q0 = *(const float4*)(Ws + k * 128 + cb);
            float4 q1 = *(const float4*)(Ws + k * 128 + cb + 4);
            float bv[8] = {q0.x, q0.y, q0.z, q0.w, q1.x, q1.y, q1.z, q1.w};
            #pragma unroll
            for (int e = 0; e < 8; ++e)
                #pragma unroll
                for (int f = 0; f < 8; ++f) acc[e][f] += av[e] * bv[f];
        }
    }

    {
        float blv[8];
        #pragma unroll
        for (int f = 0; f < 8; ++f) blv[f] = blo[cb + f];
        #pragma unroll
        for (int e = 0; e < 8; ++e) {
            float v[8];
            #pragma unroll
            for (int f = 0; f < 8; ++f)
                v[f] = zn[(mb + e) * 129 + cb + f] * (acc[e][f] + blv[f]);
            float* orow = out + (size_t)(r0 + mb + e) * 128 + cb;
            *(float4*)(orow)     = make_float4(v[0], v[1], v[2], v[3]);
            *(float4*)(orow + 4) = make_float4(v[4], v[5], v[6], v[7]);
        }
    }
}

// ---------------------------------------------------------------------------
extern "C" void kernel_launch(void* const* d_in, const int* in_sizes, int n_in,
                              void* d_out, int out_size)
{
    const float* z    = (const float*)d_in[0];
    const float* lnw  = (const float*)d_in[1];
    const float* lnb  = (const float*)d_in[2];
    const float* Wga  = (const float*)d_in[3];
    const float* bga  = (const float*)d_in[4];
    const float* Wla  = (const float*)d_in[5];
    const float* bla  = (const float*)d_in[6];
    const float* Wgb  = (const float*)d_in[7];
    const float* bgb  = (const float*)d_in[8];
    const float* Wlb  = (const float*)d_in[9];
    const float* blb  = (const float*)d_in[10];
    const float* lnow = (const float*)d_in[11];
    const float* lnob = (const float*)d_in[12];
    const float* Wgo  = (const float*)d_in[13];
    const float* bgo  = (const float*)d_in[14];
    const float* Wlo  = (const float*)d_in[15];
    const float* blo  = (const float*)d_in[16];
    float* out = (float*)d_out;

    const size_t smemA = (size_t)(128 * 129 + 128 * 128 + 128 * 129) * sizeof(float);
    cudaFuncSetAttribute(k_ln_proj_ab, cudaFuncAttributeMaxDynamicSharedMemorySize, (int)smemA);
    cudaFuncSetAttribute(k_final,      cudaFuncAttributeMaxDynamicSharedMemorySize, (int)smemA);

    k_ln_proj_ab<<<2048, 256, smemA>>>(z, lnw, lnb, Wga, bga, Wla, bla, Wgb, bgb, Wlb, blb);
    k_transpose_b<<<dim3(16, 16, 128), 256>>>();
    k_einsum_mma<<<dim3(4, 4, 128), 256>>>();
    k_final<<<2048, 256, smemA>>>(z, lnw, lnb, lnow, lnob, Wgo, bgo, Wlo, blo, out);
}

// round 5
// speedup vs baseline: 2.1701x; 1.7082x over previous
#include <cuda_runtime.h>
#include <cstdint>

#define LQ 512
#define LLQ (512*512)
#define PAD 132    // fragment-clean stride: (4*group + tig) all distinct mod 32
#define KPAD 129   // gather-clean stride for kn

// channel-major scratch
__device__ float g_a [(size_t)128 * LLQ];   // a [c][i][m]   (tf32-rounded)
__device__ float g_b [(size_t)128 * LLQ];   // b [c][m][j]   (fp32)
__device__ float g_bt[(size_t)128 * LLQ];   // b^T [c][j][m] (tf32-rounded)
__device__ float g_k [(size_t)128 * LLQ];   // k [c][i][j]   (fp32)

__device__ __forceinline__ float sigmoidf_(float x) {
    return 1.0f / (1.0f + __expf(-x));
}

__device__ __forceinline__ float to_tf32(float x) {
    uint32_t u;
    asm("cvt.rna.tf32.f32 %0, %1;" : "=r"(u) : "f"(x));
    return __uint_as_float(u);
}

// warp-level tf32 MMA: D(16x8) += A(16x8) * B(8x8), row.col
__device__ __forceinline__ void mma_tf32(float* d, uint32_t a0, uint32_t a1, uint32_t a2, uint32_t a3,
                                         uint32_t b0, uint32_t b1) {
    asm volatile(
        "mma.sync.aligned.m16n8k8.row.col.f32.tf32.tf32.f32 "
        "{%0,%1,%2,%3}, {%4,%5,%6,%7}, {%8,%9}, {%0,%1,%2,%3};"
        : "+f"(d[0]), "+f"(d[1]), "+f"(d[2]), "+f"(d[3])
        : "r"(a0), "r"(a1), "r"(a2), "r"(a3), "r"(b0), "r"(b1));
}

// ---------------------------------------------------------------------------
// Kernel 1: LN(z) + 4 gated projections (mma.sync TF32) -> a,b channel-major
// 256 threads = 8 warps (4m x 2n), warp tile 32x64, K=128
// smem: zn[128][PAD] + Wt[128][PAD]
// ---------------------------------------------------------------------------
__global__ void __launch_bounds__(256) k_ln_proj_ab(
    const float* __restrict__ z,
    const float* __restrict__ lnw, const float* __restrict__ lnb,
    const float* __restrict__ Wga, const float* __restrict__ bga,
    const float* __restrict__ Wla, const float* __restrict__ bla,
    const float* __restrict__ Wgb, const float* __restrict__ bgb,
    const float* __restrict__ Wlb, const float* __restrict__ blb)
{
    extern __shared__ float sm[];
    float* zn = sm;                 // [128][PAD] tf32-rounded LN output
    float* Wt = sm + 128 * PAD;     // [128][PAD] transposed weight (n-major)

    const int tid  = threadIdx.x;
    const int r0   = blockIdx.x * 128;
    const int lane = tid & 31, warp = tid >> 5;

    // ---- layernorm -> zn (tf32 rounded) ----
    {
        const float w0 = lnw[lane], w1 = lnw[lane + 32], w2 = lnw[lane + 64], w3 = lnw[lane + 96];
        const float c0 = lnb[lane], c1 = lnb[lane + 32], c2 = lnb[lane + 64], c3 = lnb[lane + 96];
        for (int it = 0; it < 16; ++it) {
            int row = warp * 16 + it;
            const float* zr = z + (size_t)(r0 + row) * 128;
            float x0 = zr[lane], x1 = zr[lane + 32], x2 = zr[lane + 64], x3 = zr[lane + 96];
            float s = x0 + x1 + x2 + x3;
            float q = x0 * x0 + x1 * x1 + x2 * x2 + x3 * x3;
            #pragma unroll
            for (int o = 16; o > 0; o >>= 1) {
                s += __shfl_xor_sync(0xffffffffu, s, o);
                q += __shfl_xor_sync(0xffffffffu, q, o);
            }
            float mu  = s * (1.0f / 128.0f);
            float var = q * (1.0f / 128.0f) - mu * mu;
            float rs  = rsqrtf(var + 1e-5f);
            float* zo = zn + row * PAD;
            zo[lane]      = to_tf32((x0 - mu) * rs * w0 + c0);
            zo[lane + 32] = to_tf32((x1 - mu) * rs * w1 + c1);
            zo[lane + 64] = to_tf32((x2 - mu) * rs * w2 + c2);
            zo[lane + 96] = to_tf32((x3 - mu) * rs * w3 + c3);
        }
    }

    const int wm = warp & 3, wn = warp >> 2;
    const int group = lane >> 2, tig = lane & 3;
    const int arow0 = wm * 32 + group;    // +0 / +16 for the two m-subtiles
    const int brow0 = wn * 64 + group;    // + u*8

    #pragma unroll 1
    for (int p = 0; p < 2; ++p) {
        const float* Wg = p ? Wgb : Wga;
        const float* bg = p ? bgb : bga;
        const float* Wl = p ? Wlb : Wla;
        const float* bl = p ? blb : bla;
        float* dst = p ? g_b : g_a;

        // ---- stage Wg^T ----
        __syncthreads();   // zn ready (p=0) / previous fragment reads done (p=1)
        for (int it = 0; it < 64; ++it) {
            int idx = it * 256 + tid;
            int k = idx >> 7, n = idx & 127;
            Wt[n * PAD + k] = to_tf32(Wg[idx]);
        }
        __syncthreads();

        float accg[2][8][4];
        #pragma unroll
        for (int t = 0; t < 2; ++t)
            #pragma unroll
            for (int u = 0; u < 8; ++u)
                #pragma unroll
                for (int v = 0; v < 4; ++v) accg[t][u][v] = 0.0f;

        #pragma unroll
        for (int ks = 0; ks < 16; ++ks) {
            const int k = ks * 8;
            uint32_t af[2][4];
            #pragma unroll
            for (int t = 0; t < 2; ++t) {
                int ra = arow0 + t * 16;
                af[t][0] = __float_as_uint(zn[ra * PAD + k + tig]);
                af[t][1] = __float_as_uint(zn[(ra + 8) * PAD + k + tig]);
                af[t][2] = __float_as_uint(zn[ra * PAD + k + tig + 4]);
                af[t][3] = __float_as_uint(zn[(ra + 8) * PAD + k + tig + 4]);
            }
            #pragma unroll
            for (int u = 0; u < 8; ++u) {
                int rb = brow0 + u * 8;
                uint32_t b0 = __float_as_uint(Wt[rb * PAD + k + tig]);
                uint32_t b1 = __float_as_uint(Wt[rb * PAD + k + tig + 4]);
                mma_tf32(accg[0][u], af[0][0], af[0][1], af[0][2], af[0][3], b0, b1);
                mma_tf32(accg[1][u], af[1][0], af[1][1], af[1][2], af[1][3], b0, b1);
            }
        }
        __syncthreads();   // Wt reads done

        // ---- stage Wl^T ----
        for (int it = 0; it < 64; ++it) {
            int idx = it * 256 + tid;
            int k = idx >> 7, n = idx & 127;
            Wt[n * PAD + k] = to_tf32(Wl[idx]);
        }
        __syncthreads();

        float accl[2][8][4];
        #pragma unroll
        for (int t = 0; t < 2; ++t)
            #pragma unroll
            for (int u = 0; u < 8; ++u)
                #pragma unroll
                for (int v = 0; v < 4; ++v) accl[t][u][v] = 0.0f;

        #pragma unroll
        for (int ks = 0; ks < 16; ++ks) {
            const int k = ks * 8;
            uint32_t af[2][4];
            #pragma unroll
            for (int t = 0; t < 2; ++t) {
                int ra = arow0 + t * 16;
                af[t][0] = __float_as_uint(zn[ra * PAD + k + tig]);
                af[t][1] = __float_as_uint(zn[(ra + 8) * PAD + k + tig]);
                af[t][2] = __float_as_uint(zn[ra * PAD + k + tig + 4]);
                af[t][3] = __float_as_uint(zn[(ra + 8) * PAD + k + tig + 4]);
            }
            #pragma unroll
            for (int u = 0; u < 8; ++u) {
                int rb = brow0 + u * 8;
                uint32_t b0 = __float_as_uint(Wt[rb * PAD + k + tig]);
                uint32_t b1 = __float_as_uint(Wt[rb * PAD + k + tig + 4]);
                mma_tf32(accl[0][u], af[0][0], af[0][1], af[0][2], af[0][3], b0, b1);
                mma_tf32(accl[1][u], af[1][0], af[1][1], af[1][2], af[1][3], b0, b1);
            }
        }

        // ---- combine + channel-major store ----
        #pragma unroll
        for (int u = 0; u < 8; ++u) {
            const int col = wn * 64 + u * 8 + tig * 2;
            const float bg0 = bg[col], bg1 = bg[col + 1];
            const float bl0 = bl[col], bl1 = bl[col + 1];
            #pragma unroll
            for (int t = 0; t < 2; ++t) {
                const int row = r0 + wm * 32 + t * 16 + group;
                float v0 = sigmoidf_(accg[t][u][0] + bg0) * (accl[t][u][0] + bl0);
                float v1 = sigmoidf_(accg[t][u][1] + bg1) * (accl[t][u][1] + bl1);
                float v2 = sigmoidf_(accg[t][u][2] + bg0) * (accl[t][u][2] + bl0);
                float v3 = sigmoidf_(accg[t][u][3] + bg1) * (accl[t][u][3] + bl1);
                if (p == 0) { v0 = to_tf32(v0); v1 = to_tf32(v1); v2 = to_tf32(v2); v3 = to_tf32(v3); }
                dst[(size_t)col       * LLQ + row]     = v0;
                dst[(size_t)(col + 1) * LLQ + row]     = v1;
                dst[(size_t)col       * LLQ + row + 8] = v2;
                dst[(size_t)(col + 1) * LLQ + row + 8] = v3;
            }
        }
    }
}

// ---------------------------------------------------------------------------
// Transpose: g_b [c][m][j] -> g_bt [c][j][m], tf32-rounded
// ---------------------------------------------------------------------------
__global__ void __launch_bounds__(256) k_transpose_b()
{
    __shared__ float t[32][33];
    const int c  = blockIdx.z;
    const int m0 = blockIdx.y * 32;
    const int j0 = blockIdx.x * 32;
    const int tx = threadIdx.x & 31, ty = threadIdx.x >> 5;

    const float* src = g_b + (size_t)c * LLQ;
    float*       dst = g_bt + (size_t)c * LLQ;

    #pragma unroll
    for (int r = 0; r < 4; ++r) {
        int m = ty * 4 + r;
        t[m][tx] = src[(size_t)(m0 + m) * LQ + j0 + tx];
    }
    __syncthreads();
    #pragma unroll
    for (int r = 0; r < 4; ++r) {
        int j = ty * 4 + r;
        dst[(size_t)(j0 + j) * LQ + m0 + tx] = to_tf32(t[tx][j]);
    }
}

// ---------------------------------------------------------------------------
// Kernel 2: mma.sync TF32 einsum. Per CTA: 128x128 tile of K_c = A_c @ B_c^T
// ---------------------------------------------------------------------------
#define EPAD 36

__global__ void __launch_bounds__(256, 2) k_einsum_mma()
{
    __shared__ float As[128 * EPAD];
    __shared__ float Bs[128 * EPAD];

    const int tid  = threadIdx.x;
    const int lane = tid & 31, warp = tid >> 5;
    const int wm = warp & 3;
    const int wn = warp >> 2;
    const int c  = blockIdx.z;
    const int i0 = blockIdx.y * 128;
    const int j0 = blockIdx.x * 128;

    const float* A  = g_a  + (size_t)c * LLQ;
    const float* Bt = g_bt + (size_t)c * LLQ;

    float4 pa[4], pb[4];
    #pragma unroll
    for (int r = 0; r < 4; ++r) {
        int idx = r * 256 + tid;
        int row = idx >> 3, q = idx & 7;
        pa[r] = *(const float4*)(A  + (size_t)(i0 + row) * LQ + q * 4);
        pb[r] = *(const float4*)(Bt + (size_t)(j0 + row) * LQ + q * 4);
    }

    float acc[2][8][4];
    #pragma unroll
    for (int t = 0; t < 2; ++t)
        #pragma unroll
        for (int u = 0; u < 8; ++u)
            #pragma unroll
            for (int v = 0; v < 4; ++v) acc[t][u][v] = 0.0f;

    const int arow0 = wm * 32 + (lane >> 2);
    const int acol  = lane & 3;
    const int brow0 = wn * 64 + (lane >> 2);

    #pragma unroll 1
    for (int kt = 0; kt < 16; ++kt) {
        #pragma unroll
        for (int r = 0; r < 4; ++r) {
            int idx = r * 256 + tid;
            int row = idx >> 3, q = idx & 7;
            *(float4*)(As + row * EPAD + q * 4) = pa[r];
            *(float4*)(Bs + row * EPAD + q * 4) = pb[r];
        }
        __syncthreads();

        if (kt < 15) {
            int k0 = (kt + 1) * 32;
            #pragma unroll
            for (int r = 0; r < 4; ++r) {
                int idx = r * 256 + tid;
                int row = idx >> 3, q = idx & 7;
                pa[r] = *(const float4*)(A  + (size_t)(i0 + row) * LQ + k0 + q * 4);
                pb[r] = *(const float4*)(Bt + (size_t)(j0 + row) * LQ + k0 + q * 4);
            }
        }

        #pragma unroll
        for (int ks = 0; ks < 4; ++ks) {
            const int k = ks * 8;
            uint32_t af[2][4];
            #pragma unroll
            for (int t = 0; t < 2; ++t) {
                int ra = arow0 + t * 16;
                af[t][0] = __float_as_uint(As[ra * EPAD + k + acol]);
                af[t][1] = __float_as_uint(As[(ra + 8) * EPAD + k + acol]);
                af[t][2] = __float_as_uint(As[ra * EPAD + k + acol + 4]);
                af[t][3] = __float_as_uint(As[(ra + 8) * EPAD + k + acol + 4]);
            }
            #pragma unroll
            for (int u = 0; u < 8; ++u) {
                int rb = brow0 + u * 8;
                uint32_t b0 = __float_as_uint(Bs[rb * EPAD + k + acol]);
                uint32_t b1 = __float_as_uint(Bs[rb * EPAD + k + acol + 4]);
                mma_tf32(acc[0][u], af[0][0], af[0][1], af[0][2], af[0][3], b0, b1);
                mma_tf32(acc[1][u], af[1][0], af[1][1], af[1][2], af[1][3], b0, b1);
            }
        }
        __syncthreads();
    }

    float* K = g_k + (size_t)c * LLQ;
    const int orow = i0 + wm * 32 + (lane >> 2);
    const int ocol = j0 + wn * 64 + (lane & 3) * 2;
    #pragma unroll
    for (int t = 0; t < 2; ++t) {
        #pragma unroll
        for (int u = 0; u < 8; ++u) {
            float* p0 = K + (size_t)(orow + t * 16)     * LQ + ocol + u * 8;
            float* p1 = K + (size_t)(orow + t * 16 + 8) * LQ + ocol + u * 8;
            *(float2*)p0 = make_float2(acc[t][u][0], acc[t][u][1]);
            *(float2*)p1 = make_float2(acc[t][u][2], acc[t][u][3]);
        }
    }
}

// ---------------------------------------------------------------------------
// Kernel 3: out = sigmoid(LN(z)@Wgo + bgo) * (LN(k)@Wlo + blo)  (mma.sync TF32)
// smem: zn[128][PAD] + kn[128][KPAD] + Wt[128][PAD]
// ---------------------------------------------------------------------------
__global__ void __launch_bounds__(256) k_final(
    const float* __restrict__ z,
    const float* __restrict__ lnw, const float* __restrict__ lnb,
    const float* __restrict__ lnow, const float* __restrict__ lnob,
    const float* __restrict__ Wgo, const float* __restrict__ bgo,
    const float* __restrict__ Wlo, const float* __restrict__ blo,
    float* __restrict__ out)
{
    extern __shared__ float sm[];
    float* zn = sm;                          // [128][PAD]
    float* kn = sm + 128 * PAD;              // [128][KPAD]
    float* Wt = sm + 128 * PAD + 128 * KPAD; // [128][PAD]

    const int tid  = threadIdx.x;
    const int r0   = blockIdx.x * 128;
    const int i    = r0 >> 9;
    const int j0   = r0 & 511;
    const int lane = tid & 31, warp = tid >> 5;

    // LN(z) -> zn (tf32)
    {
        const float w0 = lnw[lane], w1 = lnw[lane + 32], w2 = lnw[lane + 64], w3 = lnw[lane + 96];
        const float c0 = lnb[lane], c1 = lnb[lane + 32], c2 = lnb[lane + 64], c3 = lnb[lane + 96];
        for (int it = 0; it < 16; ++it) {
            int row = warp * 16 + it;
            const float* zr = z + (size_t)(r0 + row) * 128;
            float x0 = zr[lane], x1 = zr[lane + 32], x2 = zr[lane + 64], x3 = zr[lane + 96];
            float s = x0 + x1 + x2 + x3;
            float q = x0 * x0 + x1 * x1 + x2 * x2 + x3 * x3;
            #pragma unroll
            for (int o = 16; o > 0; o >>= 1) {
                s += __shfl_xor_sync(0xffffffffu, s, o);
                q += __shfl_xor_sync(0xffffffffu, q, o);
            }
            float mu  = s * (1.0f / 128.0f);
            float var = q * (1.0f / 128.0f) - mu * mu;
            float rs  = rsqrtf(var + 1e-5f);
            float* zo = zn + row * PAD;
            zo[lane]      = to_tf32((x0 - mu) * rs * w0 + c0);
            zo[lane + 32] = to_tf32((x1 - mu) * rs * w1 + c1);
            zo[lane + 64] = to_tf32((x2 - mu) * rs * w2 + c2);
            zo[lane + 96] = to_tf32((x3 - mu) * rs * w3 + c3);
        }
    }

    // gather k tile (channel-major -> row-major)
    for (int it = 0; it < 64; ++it) {
        int idx = it * 256 + tid;
        int jl = idx & 127;
        int c  = idx >> 7;
        kn[jl * KPAD + c] = g_k[(size_t)c * LLQ + (size_t)i * LQ + j0 + jl];
    }
    __syncthreads();

    // LN(k) in place (tf32)
    {
        const float w0 = lnow[lane], w1 = lnow[lane + 32], w2 = lnow[lane + 64], w3 = lnow[lane + 96];
        const float c0 = lnob[lane], c1 = lnob[lane + 32], c2 = lnob[lane + 64], c3 = lnob[lane + 96];
        for (int it = 0; it < 16; ++it) {
            int row = warp * 16 + it;
            float* kr = kn + row * KPAD;
            float x0 = kr[lane], x1 = kr[lane + 32], x2 = kr[lane + 64], x3 = kr[lane + 96];
            float s = x0 + x1 + x2 + x3;
            float q = x0 * x0 + x1 * x1 + x2 * x2 + x3 * x3;
            #pragma unroll
            for (int o = 16; o > 0; o >>= 1) {
                s += __shfl_xor_sync(0xffffffffu, s, o);
                q += __shfl_xor_sync(0xffffffffu, q, o);
            }
            float mu  = s * (1.0f / 128.0f);
            float var = q * (1.0f / 128.0f) - mu * mu;
            float rs  = rsqrtf(var + 1e-5f);
            kr[lane]      = to_tf32((x0 - mu) * rs * w0 + c0);
            kr[lane + 32] = to_tf32((x1 - mu) * rs * w1 + c1);
            kr[lane + 64] = to_tf32((x2 - mu) * rs * w2 + c2);
            kr[lane + 96] = to_tf32((x3 - mu) * rs * w3 + c3);
        }
    }

    // stage Wgo^T
    for (int it = 0; it < 64; ++it) {
        int idx = it * 256 + tid;
        int k = idx >> 7, n = idx & 127;
        Wt[n * PAD + k] = to_tf32(Wgo[idx]);
    }
    __syncthreads();

    const int wm = warp & 3, wn = warp >> 2;
    const int group = lane >> 2, tig = lane & 3;
    const int arow0 = wm * 32 + group;
    const int brow0 = wn * 64 + group;

    float accg[2][8][4];
    #pragma unroll
    for (int t = 0; t < 2; ++t)
        #pragma unroll
        for (int u = 0; u < 8; ++u)
            #pragma unroll
            for (int v = 0; v < 4; ++v) accg[t][u][v] = 0.0f;

    #pragma unroll
    for (int ks = 0; ks < 16; ++ks) {
        const int k = ks * 8;
        uint32_t af[2][4];
        #pragma unroll
        for (int t = 0; t < 2; ++t) {
            int ra = arow0 + t * 16;
            af[t][0] = __float_as_uint(zn[ra * PAD + k + tig]);
            af[t][1] = __float_as_uint(zn[(ra + 8) * PAD + k + tig]);
            af[t][2] = __float_as_uint(zn[ra * PAD + k + tig + 4]);
            af[t][3] = __float_as_uint(zn[(ra + 8) * PAD + k + tig + 4]);
        }
        #pragma unroll
        for (int u = 0; u < 8; ++u) {
            int rb = brow0 + u * 8;
            uint32_t b0 = __float_as_uint(Wt[rb * PAD + k + tig]);
            uint32_t b1 = __float_as_uint(Wt[rb * PAD + k + tig + 4]);
            mma_tf32(accg[0][u], af[0][0], af[0][1], af[0][2], af[0][3], b0, b1);
            mma_tf32(accg[1][u], af[1][0], af[1][1], af[1][2], af[1][3], b0, b1);
        }
    }
    __syncthreads();

    // stage Wlo^T
    for (int it = 0; it < 64; ++it) {
        int idx = it * 256 + tid;
        int k = idx >> 7, n = idx & 127;
        Wt[n * PAD + k] = to_tf32(Wlo[idx]);
    }
    __syncthreads();

    float accl[2][8][4];
    #pragma unroll
    for (int t = 0; t < 2; ++t)
        #pragma unroll
        for (int u = 0; u < 8; ++u)
            #pragma unroll
            for (int v = 0; v < 4; ++v) accl[t][u][v] = 0.0f;

    #pragma unroll
    for (int ks = 0; ks < 16; ++ks) {
        const int k = ks * 8;
        uint32_t af[2][4];
        #pragma unroll
        for (int t = 0; t < 2; ++t) {
            int ra = arow0 + t * 16;
            af[t][0] = __float_as_uint(kn[ra * KPAD + k + tig]);
            af[t][1] = __float_as_uint(kn[(ra + 8) * KPAD + k + tig]);
            af[t][2] = __float_as_uint(kn[ra * KPAD + k + tig + 4]);
            af[t][3] = __float_as_uint(kn[(ra + 8) * KPAD + k + tig + 4]);
        }
        #pragma unroll
        for (int u = 0; u < 8; ++u) {
            int rb = brow0 + u * 8;
            uint32_t b0 = __float_as_uint(Wt[rb * PAD + k + tig]);
            uint32_t b1 = __float_as_uint(Wt[rb * PAD + k + tig + 4]);
            mma_tf32(accl[0][u], af[0][0], af[0][1], af[0][2], af[0][3], b0, b1);
            mma_tf32(accl[1][u], af[1][0], af[1][1], af[1][2], af[1][3], b0, b1);
        }
    }

    // combine + store (row-major out)
    #pragma unroll
    for (int u = 0; u < 8; ++u) {
        const int col = wn * 64 + u * 8 + tig * 2;
        const float bg0 = bgo[col], bg1 = bgo[col + 1];
        const float bl0 = blo[col], bl1 = blo[col + 1];
        #pragma unroll
        for (int t = 0; t < 2; ++t) {
            const int row = r0 + wm * 32 + t * 16 + group;
            float v0 = sigmoidf_(accg[t][u][0] + bg0) * (accl[t][u][0] + bl0);
            float v1 = sigmoidf_(accg[t][u][1] + bg1) * (accl[t][u][1] + bl1);
            float v2 = sigmoidf_(accg[t][u][2] + bg0) * (accl[t][u][2] + bl0);
            float v3 = sigmoidf_(accg[t][u][3] + bg1) * (accl[t][u][3] + bl1);
            *(float2*)(out + (size_t)row * 128 + col)       = make_float2(v0, v1);
            *(float2*)(out + (size_t)(row + 8) * 128 + col) = make_float2(v2, v3);
        }
    }
}

// ---------------------------------------------------------------------------
extern "C" void kernel_launch(void* const* d_in, const int* in_sizes, int n_in,
                              void* d_out, int out_size)
{
    const float* z    = (const float*)d_in[0];
    const float* lnw  = (const float*)d_in[1];
    const float* lnb  = (const float*)d_in[2];
    const float* Wga  = (const float*)d_in[3];
    const float* bga  = (const float*)d_in[4];
    const float* Wla  = (const float*)d_in[5];
    const float* bla  = (const float*)d_in[6];
    const float* Wgb  = (const float*)d_in[7];
    const float* bgb  = (const float*)d_in[8];
    const float* Wlb  = (const float*)d_in[9];
    const float* blb  = (const float*)d_in[10];
    const float* lnow = (const float*)d_in[11];
    const float* lnob = (const float*)d_in[12];
    const float* Wgo  = (const float*)d_in[13];
    const float* bgo  = (const float*)d_in[14];
    const float* Wlo  = (const float*)d_in[15];
    const float* blo  = (const float*)d_in[16];
    float* out = (float*)d_out;

    const size_t smem1 = (size_t)(128 * PAD * 2) * sizeof(float);                 // 135168
    const size_t smem3 = (size_t)(128 * PAD * 2 + 128 * KPAD) * sizeof(float);    // 201216
    cudaFuncSetAttribute(k_ln_proj_ab, cudaFuncAttributeMaxDynamicSharedMemorySize, (int)smem1);
    cudaFuncSetAttribute(k_final,      cudaFuncAttributeMaxDynamicSharedMemorySize, (int)smem3);

    k_ln_proj_ab<<<2048, 256, smem1>>>(z, lnw, lnb, Wga, bga, Wla, bla, Wgb, bgb, Wlb, blb);
    k_transpose_b<<<dim3(16, 16, 128), 256>>>();
    k_einsum_mma<<<dim3(4, 4, 128), 256>>>();
    k_final<<<2048, 256, smem3>>>(z, lnw, lnb, lnow, lnob, Wgo, bgo, Wlo, blo, out);
}

// round 6
// speedup vs baseline: 2.4717x; 1.1390x over previous
#include <cuda_runtime.h>
#include <cstdint>

#define LQ 512
#define LLQ (512*512)
#define PAD 132    // fragment-clean stride
#define KPAD 130   // 2-way/2-way compromise stride for kn

// channel-major scratch
__device__ float g_a [(size_t)128 * LLQ];   // a [c][i][m]   (tf32-rounded)
__device__ float g_b [(size_t)128 * LLQ];   // b [c][m][j]   (fp32)
__device__ float g_bt[(size_t)128 * LLQ];   // b^T [c][j][m] (tf32-rounded)
__device__ float g_k [(size_t)128 * LLQ];   // k [c][i][j]   (fp32)

__device__ __forceinline__ float sigmoidf_(float x) {
    return 1.0f / (1.0f + __expf(-x));
}

__device__ __forceinline__ float to_tf32(float x) {
    uint32_t u;
    asm("cvt.rna.tf32.f32 %0, %1;" : "=r"(u) : "f"(x));
    return __uint_as_float(u);
}

// warp-level tf32 MMA: D(16x8) += A(16x8) * B(8x8), row.col
__device__ __forceinline__ void mma_tf32(float* d, uint32_t a0, uint32_t a1, uint32_t a2, uint32_t a3,
                                         uint32_t b0, uint32_t b1) {
    asm volatile(
        "mma.sync.aligned.m16n8k8.row.col.f32.tf32.tf32.f32 "
        "{%0,%1,%2,%3}, {%4,%5,%6,%7}, {%8,%9}, {%0,%1,%2,%3};"
        : "+f"(d[0]), "+f"(d[1]), "+f"(d[2]), "+f"(d[3])
        : "r"(a0), "r"(a1), "r"(a2), "r"(a3), "r"(b0), "r"(b1));
}

// ---------------------------------------------------------------------------
// Kernel 1: LN(z) + 4 gated projections (mma.sync TF32) -> a,b channel-major
// 512 threads = 16 warps (8m x 2n), warp tile 16x64, K=128
// smem: zn[128][PAD] + Wt[128][PAD]
// ---------------------------------------------------------------------------
__global__ void __launch_bounds__(512, 1) k_ln_proj_ab(
    const float* __restrict__ z,
    const float* __restrict__ lnw, const float* __restrict__ lnb,
    const float* __restrict__ Wga, const float* __restrict__ bga,
    const float* __restrict__ Wla, const float* __restrict__ bla,
    const float* __restrict__ Wgb, const float* __restrict__ bgb,
    const float* __restrict__ Wlb, const float* __restrict__ blb)
{
    extern __shared__ float sm[];
    float* zn = sm;                 // [128][PAD]
    float* Wt = sm + 128 * PAD;     // [128][PAD]

    const int tid  = threadIdx.x;
    const int r0   = blockIdx.x * 128;
    const int lane = tid & 31, warp = tid >> 5;

    // ---- layernorm -> zn (tf32 rounded), 8 rows per warp ----
    {
        const float w0 = lnw[lane], w1 = lnw[lane + 32], w2 = lnw[lane + 64], w3 = lnw[lane + 96];
        const float c0 = lnb[lane], c1 = lnb[lane + 32], c2 = lnb[lane + 64], c3 = lnb[lane + 96];
        for (int it = 0; it < 8; ++it) {
            int row = warp * 8 + it;
            const float* zr = z + (size_t)(r0 + row) * 128;
            float x0 = zr[lane], x1 = zr[lane + 32], x2 = zr[lane + 64], x3 = zr[lane + 96];
            float s = x0 + x1 + x2 + x3;
            float q = x0 * x0 + x1 * x1 + x2 * x2 + x3 * x3;
            #pragma unroll
            for (int o = 16; o > 0; o >>= 1) {
                s += __shfl_xor_sync(0xffffffffu, s, o);
                q += __shfl_xor_sync(0xffffffffu, q, o);
            }
            float mu  = s * (1.0f / 128.0f);
            float var = q * (1.0f / 128.0f) - mu * mu;
            float rs  = rsqrtf(var + 1e-5f);
            float* zo = zn + row * PAD;
            zo[lane]      = to_tf32((x0 - mu) * rs * w0 + c0);
            zo[lane + 32] = to_tf32((x1 - mu) * rs * w1 + c1);
            zo[lane + 64] = to_tf32((x2 - mu) * rs * w2 + c2);
            zo[lane + 96] = to_tf32((x3 - mu) * rs * w3 + c3);
        }
    }

    const int wm = warp >> 1, wn = warp & 1;   // 8 m-tiles x 2 n-tiles
    const int group = lane >> 2, tig = lane & 3;
    const int arow0 = wm * 16 + group;
    const int brow0 = wn * 64 + group;

    #pragma unroll 1
    for (int p = 0; p < 2; ++p) {
        const float* Wg = p ? Wgb : Wga;
        const float* bg = p ? bgb : bga;
        const float* Wl = p ? Wlb : Wla;
        const float* bl = p ? blb : bla;
        float* dst = p ? g_b : g_a;

        // ---- stage Wg^T ----
        __syncthreads();
        for (int it = 0; it < 32; ++it) {
            int idx = it * 512 + tid;
            int k = idx >> 7, n = idx & 127;
            Wt[n * PAD + k] = to_tf32(Wg[idx]);
        }
        __syncthreads();

        float accg[8][4];
        #pragma unroll
        for (int u = 0; u < 8; ++u)
            #pragma unroll
            for (int v = 0; v < 4; ++v) accg[u][v] = 0.0f;

        #pragma unroll
        for (int ks = 0; ks < 16; ++ks) {
            const int k = ks * 8;
            uint32_t a0 = __float_as_uint(zn[arow0 * PAD + k + tig]);
            uint32_t a1 = __float_as_uint(zn[(arow0 + 8) * PAD + k + tig]);
            uint32_t a2 = __float_as_uint(zn[arow0 * PAD + k + tig + 4]);
            uint32_t a3 = __float_as_uint(zn[(arow0 + 8) * PAD + k + tig + 4]);
            #pragma unroll
            for (int u = 0; u < 8; ++u) {
                int rb = brow0 + u * 8;
                uint32_t b0 = __float_as_uint(Wt[rb * PAD + k + tig]);
                uint32_t b1 = __float_as_uint(Wt[rb * PAD + k + tig + 4]);
                mma_tf32(accg[u], a0, a1, a2, a3, b0, b1);
            }
        }
        __syncthreads();

        // ---- stage Wl^T ----
        for (int it = 0; it < 32; ++it) {
            int idx = it * 512 + tid;
            int k = idx >> 7, n = idx & 127;
            Wt[n * PAD + k] = to_tf32(Wl[idx]);
        }
        __syncthreads();

        float accl[8][4];
        #pragma unroll
        for (int u = 0; u < 8; ++u)
            #pragma unroll
            for (int v = 0; v < 4; ++v) accl[u][v] = 0.0f;

        #pragma unroll
        for (int ks = 0; ks < 16; ++ks) {
            const int k = ks * 8;
            uint32_t a0 = __float_as_uint(zn[arow0 * PAD + k + tig]);
            uint32_t a1 = __float_as_uint(zn[(arow0 + 8) * PAD + k + tig]);
            uint32_t a2 = __float_as_uint(zn[arow0 * PAD + k + tig + 4]);
            uint32_t a3 = __float_as_uint(zn[(arow0 + 8) * PAD + k + tig + 4]);
            #pragma unroll
            for (int u = 0; u < 8; ++u) {
                int rb = brow0 + u * 8;
                uint32_t b0 = __float_as_uint(Wt[rb * PAD + k + tig]);
                uint32_t b1 = __float_as_uint(Wt[rb * PAD + k + tig + 4]);
                mma_tf32(accl[u], a0, a1, a2, a3, b0, b1);
            }
        }

        // ---- combine + channel-major store ----
        #pragma unroll
        for (int u = 0; u < 8; ++u) {
            const int col = wn * 64 + u * 8 + tig * 2;
            const float bg0 = bg[col], bg1 = bg[col + 1];
            const float bl0 = bl[col], bl1 = bl[col + 1];
            const int row = r0 + wm * 16 + group;
            float v0 = sigmoidf_(accg[u][0] + bg0) * (accl[u][0] + bl0);
            float v1 = sigmoidf_(accg[u][1] + bg1) * (accl[u][1] + bl1);
            float v2 = sigmoidf_(accg[u][2] + bg0) * (accl[u][2] + bl0);
            float v3 = sigmoidf_(accg[u][3] + bg1) * (accl[u][3] + bl1);
            if (p == 0) { v0 = to_tf32(v0); v1 = to_tf32(v1); v2 = to_tf32(v2); v3 = to_tf32(v3); }
            dst[(size_t)col       * LLQ + row]     = v0;
            dst[(size_t)(col + 1) * LLQ + row]     = v1;
            dst[(size_t)col       * LLQ + row + 8] = v2;
            dst[(size_t)(col + 1) * LLQ + row + 8] = v3;
        }
    }
}

// ---------------------------------------------------------------------------
// Transpose: g_b [c][m][j] -> g_bt [c][j][m], tf32-rounded
// ---------------------------------------------------------------------------
__global__ void __launch_bounds__(256) k_transpose_b()
{
    __shared__ float t[32][33];
    const int c  = blockIdx.z;
    const int m0 = blockIdx.y * 32;
    const int j0 = blockIdx.x * 32;
    const int tx = threadIdx.x & 31, ty = threadIdx.x >> 5;

    const float* src = g_b + (size_t)c * LLQ;
    float*       dst = g_bt + (size_t)c * LLQ;

    #pragma unroll
    for (int r = 0; r < 4; ++r) {
        int m = ty * 4 + r;
        t[m][tx] = src[(size_t)(m0 + m) * LQ + j0 + tx];
    }
    __syncthreads();
    #pragma unroll
    for (int r = 0; r < 4; ++r) {
        int j = ty * 4 + r;
        dst[(size_t)(j0 + j) * LQ + m0 + tx] = to_tf32(t[tx][j]);
    }
}

// ---------------------------------------------------------------------------
// Kernel 2: mma.sync TF32 einsum. Per CTA: 128x128 tile of K_c = A_c @ B_c^T
// ---------------------------------------------------------------------------
#define EPAD 36

__global__ void __launch_bounds__(256, 2) k_einsum_mma()
{
    __shared__ float As[128 * EPAD];
    __shared__ float Bs[128 * EPAD];

    const int tid  = threadIdx.x;
    const int lane = tid & 31, warp = tid >> 5;
    const int wm = warp & 3;
    const int wn = warp >> 2;
    const int c  = blockIdx.z;
    const int i0 = blockIdx.y * 128;
    const int j0 = blockIdx.x * 128;

    const float* A  = g_a  + (size_t)c * LLQ;
    const float* Bt = g_bt + (size_t)c * LLQ;

    float4 pa[4], pb[4];
    #pragma unroll
    for (int r = 0; r < 4; ++r) {
        int idx = r * 256 + tid;
        int row = idx >> 3, q = idx & 7;
        pa[r] = *(const float4*)(A  + (size_t)(i0 + row) * LQ + q * 4);
        pb[r] = *(const float4*)(Bt + (size_t)(j0 + row) * LQ + q * 4);
    }

    float acc[2][8][4];
    #pragma unroll
    for (int t = 0; t < 2; ++t)
        #pragma unroll
        for (int u = 0; u < 8; ++u)
            #pragma unroll
            for (int v = 0; v < 4; ++v) acc[t][u][v] = 0.0f;

    const int arow0 = wm * 32 + (lane >> 2);
    const int acol  = lane & 3;
    const int brow0 = wn * 64 + (lane >> 2);

    #pragma unroll 1
    for (int kt = 0; kt < 16; ++kt) {
        #pragma unroll
        for (int r = 0; r < 4; ++r) {
            int idx = r * 256 + tid;
            int row = idx >> 3, q = idx & 7;
            *(float4*)(As + row * EPAD + q * 4) = pa[r];
            *(float4*)(Bs + row * EPAD + q * 4) = pb[r];
        }
        __syncthreads();

        if (kt < 15) {
            int k0 = (kt + 1) * 32;
            #pragma unroll
            for (int r = 0; r < 4; ++r) {
                int idx = r * 256 + tid;
                int row = idx >> 3, q = idx & 7;
                pa[r] = *(const float4*)(A  + (size_t)(i0 + row) * LQ + k0 + q * 4);
                pb[r] = *(const float4*)(Bt + (size_t)(j0 + row) * LQ + k0 + q * 4);
            }
        }

        #pragma unroll
        for (int ks = 0; ks < 4; ++ks) {
            const int k = ks * 8;
            uint32_t af[2][4];
            #pragma unroll
            for (int t = 0; t < 2; ++t) {
                int ra = arow0 + t * 16;
                af[t][0] = __float_as_uint(As[ra * EPAD + k + acol]);
                af[t][1] = __float_as_uint(As[(ra + 8) * EPAD + k + acol]);
                af[t][2] = __float_as_uint(As[ra * EPAD + k + acol + 4]);
                af[t][3] = __float_as_uint(As[(ra + 8) * EPAD + k + acol + 4]);
            }
            #pragma unroll
            for (int u = 0; u < 8; ++u) {
                int rb = brow0 + u * 8;
                uint32_t b0 = __float_as_uint(Bs[rb * EPAD + k + acol]);
                uint32_t b1 = __float_as_uint(Bs[rb * EPAD + k + acol + 4]);
                mma_tf32(acc[0][u], af[0][0], af[0][1], af[0][2], af[0][3], b0, b1);
                mma_tf32(acc[1][u], af[1][0], af[1][1], af[1][2], af[1][3], b0, b1);
            }
        }
        __syncthreads();
    }

    float* K = g_k + (size_t)c * LLQ;
    const int orow = i0 + wm * 32 + (lane >> 2);
    const int ocol = j0 + wn * 64 + (lane & 3) * 2;
    #pragma unroll
    for (int t = 0; t < 2; ++t) {
        #pragma unroll
        for (int u = 0; u < 8; ++u) {
            float* p0 = K + (size_t)(orow + t * 16)     * LQ + ocol + u * 8;
            float* p1 = K + (size_t)(orow + t * 16 + 8) * LQ + ocol + u * 8;
            *(float2*)p0 = make_float2(acc[t][u][0], acc[t][u][1]);
            *(float2*)p1 = make_float2(acc[t][u][2], acc[t][u][3]);
        }
    }
}

// ---------------------------------------------------------------------------
// Kernel 3: out = sigmoid(LN(z)@Wgo + bgo) * (LN(k)@Wlo + blo)  (mma.sync TF32)
// 512 threads = 16 warps (8m x 2n), warp tile 16x64
// smem: zn[128][PAD] + kn[128][KPAD] + Wt[128][PAD]
// ---------------------------------------------------------------------------
__global__ void __launch_bounds__(512, 1) k_final(
    const float* __restrict__ z,
    const float* __restrict__ lnw, const float* __restrict__ lnb,
    const float* __restrict__ lnow, const float* __restrict__ lnob,
    const float* __restrict__ Wgo, const float* __restrict__ bgo,
    const float* __restrict__ Wlo, const float* __restrict__ blo,
    float* __restrict__ out)
{
    extern __shared__ float sm[];
    float* zn = sm;                          // [128][PAD]
    float* kn = sm + 128 * PAD;              // [128][KPAD]
    float* Wt = sm + 128 * PAD + 128 * KPAD; // [128][PAD]

    const int tid  = threadIdx.x;
    const int r0   = blockIdx.x * 128;
    const int i    = r0 >> 9;
    const int j0   = r0 & 511;
    const int lane = tid & 31, warp = tid >> 5;

    // LN(z) -> zn (tf32), 8 rows per warp
    {
        const float w0 = lnw[lane], w1 = lnw[lane + 32], w2 = lnw[lane + 64], w3 = lnw[lane + 96];
        const float c0 = lnb[lane], c1 = lnb[lane + 32], c2 = lnb[lane + 64], c3 = lnb[lane + 96];
        for (int it = 0; it < 8; ++it) {
            int row = warp * 8 + it;
            const float* zr = z + (size_t)(r0 + row) * 128;
            float x0 = zr[lane], x1 = zr[lane + 32], x2 = zr[lane + 64], x3 = zr[lane + 96];
            float s = x0 + x1 + x2 + x3;
            float q = x0 * x0 + x1 * x1 + x2 * x2 + x3 * x3;
            #pragma unroll
            for (int o = 16; o > 0; o >>= 1) {
                s += __shfl_xor_sync(0xffffffffu, s, o);
                q += __shfl_xor_sync(0xffffffffu, q, o);
            }
            float mu  = s * (1.0f / 128.0f);
            float var = q * (1.0f / 128.0f) - mu * mu;
            float rs  = rsqrtf(var + 1e-5f);
            float* zo = zn + row * PAD;
            zo[lane]      = to_tf32((x0 - mu) * rs * w0 + c0);
            zo[lane + 32] = to_tf32((x1 - mu) * rs * w1 + c1);
            zo[lane + 64] = to_tf32((x2 - mu) * rs * w2 + c2);
            zo[lane + 96] = to_tf32((x3 - mu) * rs * w3 + c3);
        }
    }

    // gather k tile (channel-major -> row-major)
    for (int it = 0; it < 32; ++it) {
        int idx = it * 512 + tid;
        int jl = idx & 127;
        int c  = idx >> 7;
        kn[jl * KPAD + c] = g_k[(size_t)c * LLQ + (size_t)i * LQ + j0 + jl];
    }
    __syncthreads();

    // LN(k) in place (tf32)
    {
        const float w0 = lnow[lane], w1 = lnow[lane + 32], w2 = lnow[lane + 64], w3 = lnow[lane + 96];
        const float c0 = lnob[lane], c1 = lnob[lane + 32], c2 = lnob[lane + 64], c3 = lnob[lane + 96];
        for (int it = 0; it < 8; ++it) {
            int row = warp * 8 + it;
            float* kr = kn + row * KPAD;
            float x0 = kr[lane], x1 = kr[lane + 32], x2 = kr[lane + 64], x3 = kr[lane + 96];
            float s = x0 + x1 + x2 + x3;
            float q = x0 * x0 + x1 * x1 + x2 * x2 + x3 * x3;
            #pragma unroll
            for (int o = 16; o > 0; o >>= 1) {
                s += __shfl_xor_sync(0xffffffffu, s, o);
                q += __shfl_xor_sync(0xffffffffu, q, o);
            }
            float mu  = s * (1.0f / 128.0f);
            float var = q * (1.0f / 128.0f) - mu * mu;
            float rs  = rsqrtf(var + 1e-5f);
            kr[lane]      = to_tf32((x0 - mu) * rs * w0 + c0);
            kr[lane + 32] = to_tf32((x1 - mu) * rs * w1 + c1);
            kr[lane + 64] = to_tf32((x2 - mu) * rs * w2 + c2);
            kr[lane + 96] = to_tf32((x3 - mu) * rs * w3 + c3);
        }
    }

    // stage Wgo^T
    for (int it = 0; it < 32; ++it) {
        int idx = it * 512 + tid;
        int k = idx >> 7, n = idx & 127;
        Wt[n * PAD + k] = to_tf32(Wgo[idx]);
    }
    __syncthreads();

    const int wm = warp >> 1, wn = warp & 1;
    const int group = lane >> 2, tig = lane & 3;
    const int arow0 = wm * 16 + group;
    const int brow0 = wn * 64 + group;

    float accg[8][4];
    #pragma unroll
    for (int u = 0; u < 8; ++u)
        #pragma unroll
        for (int v = 0; v < 4; ++v) accg[u][v] = 0.0f;

    #pragma unroll
    for (int ks = 0; ks < 16; ++ks) {
        const int k = ks * 8;
        uint32_t a0 = __float_as_uint(zn[arow0 * PAD + k + tig]);
        uint32_t a1 = __float_as_uint(zn[(arow0 + 8) * PAD + k + tig]);
        uint32_t a2 = __float_as_uint(zn[arow0 * PAD + k + tig + 4]);
        uint32_t a3 = __float_as_uint(zn[(arow0 + 8) * PAD + k + tig + 4]);
        #pragma unroll
        for (int u = 0; u < 8; ++u) {
            int rb = brow0 + u * 8;
            uint32_t b0 = __float_as_uint(Wt[rb * PAD + k + tig]);
            uint32_t b1 = __float_as_uint(Wt[rb * PAD + k + tig + 4]);
            mma_tf32(accg[u], a0, a1, a2, a3, b0, b1);
        }
    }
    __syncthreads();

    // stage Wlo^T
    for (int it = 0; it < 32; ++it) {
        int idx = it * 512 + tid;
        int k = idx >> 7, n = idx & 127;
        Wt[n * PAD + k] = to_tf32(Wlo[idx]);
    }
    __syncthreads();

    float accl[8][4];
    #pragma unroll
    for (int u = 0; u < 8; ++u)
        #pragma unroll
        for (int v = 0; v < 4; ++v) accl[u][v] = 0.0f;

    #pragma unroll
    for (int ks = 0; ks < 16; ++ks) {
        const int k = ks * 8;
        uint32_t a0 = __float_as_uint(kn[arow0 * KPAD + k + tig]);
        uint32_t a1 = __float_as_uint(kn[(arow0 + 8) * KPAD + k + tig]);
        uint32_t a2 = __float_as_uint(kn[arow0 * KPAD + k + tig + 4]);
        uint32_t a3 = __float_as_uint(kn[(arow0 + 8) * KPAD + k + tig + 4]);
        #pragma unroll
        for (int u = 0; u < 8; ++u) {
            int rb = brow0 + u * 8;
            uint32_t b0 = __float_as_uint(Wt[rb * PAD + k + tig]);
            uint32_t b1 = __float_as_uint(Wt[rb * PAD + k + tig + 4]);
            mma_tf32(accl[u], a0, a1, a2, a3, b0, b1);
        }
    }

    // combine + store (row-major out)
    #pragma unroll
    for (int u = 0; u < 8; ++u) {
        const int col = wn * 64 + u * 8 + tig * 2;
        const float bg0 = bgo[col], bg1 = bgo[col + 1];
        const float bl0 = blo[col], bl1 = blo[col + 1];
        const int row = r0 + wm * 16 + group;
        float v0 = sigmoidf_(accg[u][0] + bg0) * (accl[u][0] + bl0);
        float v1 = sigmoidf_(accg[u][1] + bg1) * (accl[u][1] + bl1);
        float v2 = sigmoidf_(accg[u][2] + bg0) * (accl[u][2] + bl0);
        float v3 = sigmoidf_(accg[u][3] + bg1) * (accl[u][3] + bl1);
        *(float2*)(out + (size_t)row * 128 + col)       = make_float2(v0, v1);
        *(float2*)(out + (size_t)(row + 8) * 128 + col) = make_float2(v2, v3);
    }
}

// ---------------------------------------------------------------------------
extern "C" void kernel_launch(void* const* d_in, const int* in_sizes, int n_in,
                              void* d_out, int out_size)
{
    const float* z    = (const float*)d_in[0];
    const float* lnw  = (const float*)d_in[1];
    const float* lnb  = (const float*)d_in[2];
    const float* Wga  = (const float*)d_in[3];
    const float* bga  = (const float*)d_in[4];
    const float* Wla  = (const float*)d_in[5];
    const float* bla  = (const float*)d_in[6];
    const float* Wgb  = (const float*)d_in[7];
    const float* bgb  = (const float*)d_in[8];
    const float* Wlb  = (const float*)d_in[9];
    const float* blb  = (const float*)d_in[10];
    const float* lnow = (const float*)d_in[11];
    const float* lnob = (const float*)d_in[12];
    const float* Wgo  = (const float*)d_in[13];
    const float* bgo  = (const float*)d_in[14];
    const float* Wlo  = (const float*)d_in[15];
    const float* blo  = (const float*)d_in[16];
    float* out = (float*)d_out;

    const size_t smem1 = (size_t)(128 * PAD * 2) * sizeof(float);
    const size_t smem3 = (size_t)(128 * PAD * 2 + 128 * KPAD) * sizeof(float);
    cudaFuncSetAttribute(k_ln_proj_ab, cudaFuncAttributeMaxDynamicSharedMemorySize, (int)smem1);
    cudaFuncSetAttribute(k_final,      cudaFuncAttributeMaxDynamicSharedMemorySize, (int)smem3);

    k_ln_proj_ab<<<2048, 512, smem1>>>(z, lnw, lnb, Wga, bga, Wla, bla, Wgb, bgb, Wlb, blb);
    k_transpose_b<<<dim3(16, 16, 128), 256>>>();
    k_einsum_mma<<<dim3(4, 4, 128), 256>>>();
    k_final<<<2048, 512, smem3>>>(z, lnw, lnb, lnow, lnob, Wgo, bgo, Wlo, blo, out);
}